// round 15
// baseline (speedup 1.0000x reference)
#include <cuda_runtime.h>
#include <math.h>

#define NBBINS 50
#define TI 64         // i-points per pcf block (= blockDim.x)
#define TILE_J 64     // j-points per block / per bbox tile
#define SORT_N 2048   // padded point count (na=nb=1536)
#define CHUNKS 64     // SORT_N / 32
#define NKEYS 257     // 256 morton cells + pad sentinel
#define MAXTILES (SORT_N / TILE_J)
#define PSLOTS 1024   // max pcf blocks (24x24=576 actual)
#define FAR_POISON 6.0e4f   // finite poison: q~-1e14 -> ex2=0, NO inf/NaN

// Scratch (device allocation forbidden).
__device__ float g_Ax[SORT_N];
__device__ float g_Ay[SORT_N];
__device__ int   g_Aorig[SORT_N];
__device__ float g_Bx[SORT_N];
__device__ float g_By[SORT_N];
__device__ int   g_Borig[SORT_N];
__device__ float g_Btile[MAXTILES * 4];        // minx, maxx, miny, maxy per j-tile
__device__ float g_wT[NBBINS * SORT_N];        // [b][i] transposed weights
__device__ float g_partT[NBBINS * PSLOTS];     // [b][slot] block partials (transposed!)

__device__ __forceinline__ double rmax_d() {
    // RMAX = 2*sqrt(1/(2*sqrt(3)*NPOINTS)), NPOINTS = 1536 in the reference.
    return 2.0 * sqrt(1.0 / (2.0 * sqrt(3.0) * 1536.0));
}

__device__ __forceinline__ unsigned spread4(unsigned v) {
    v = (v | (v << 2)) & 0x33u;
    v = (v | (v << 1)) & 0x55u;
    return v;
}

// Single MUFU.EX2; ex2(very negative) -> exact 0.
__device__ __forceinline__ float ex2(float x) {
    float r;
    asm("ex2.approx.ftz.f32 %0, %1;" : "=f"(r) : "f"(x));
    return r;
}
// Single MUFU.SQRT; sqrt.approx(0) = 0.
__device__ __forceinline__ float sqrt_approx(float x) {
    float r;
    asm("sqrt.approx.ftz.f32 %0, %1;" : "=f"(r) : "f"(x));
    return r;
}

// ---------------------------------------------------------------------------
// Kernel 0: deterministic stable counting sort (16x16 Morton) of A AND B,
// plus per-j-tile bounding boxes for B. One block, 1024 threads.
// The 257-key offset scan is a parallel Hillis-Steele (9 steps), not a
// thread-0 serial loop (which cost ~4.5us per sort in r13).
// ---------------------------------------------------------------------------
struct SortSmem {
    unsigned char cnt[NKEYS * CHUNKS];
    int rowsum[NKEYS];
    int rowoff[NKEYS];
    int sc[NKEYS];
};

__device__ void counting_sort(SortSmem* sm, const float* __restrict__ src, int n,
                              float* ox, float* oy, int* oorig) {
    const int t = threadIdx.x;
    const int lane = t & 31;

    for (int k = t; k < NKEYS * CHUNKS; k += 1024) sm->cnt[k] = 0;
    __syncthreads();

    int mykey[2];
#pragma unroll
    for (int p = 0; p < 2; ++p) {
        int idx = t + p * 1024;
        int key = 256;                               // pad sentinel, sorts last
        if (idx < n) {
            float x = src[idx * 3 + 0];
            float y = src[idx * 3 + 1];
            int cx = min(15, max(0, (int)(x * 16.0f)));
            int cy = min(15, max(0, (int)(y * 16.0f)));
            key = (int)((spread4((unsigned)cy) << 1) | spread4((unsigned)cx));
        }
        mykey[p] = key;
        unsigned mask = __match_any_sync(0xffffffffu, key);
        if (lane == __ffs(mask) - 1)
            sm->cnt[key * CHUNKS + (idx >> 5)] = (unsigned char)__popc(mask);
    }
    __syncthreads();

    if (t < NKEYS) {
        int s = 0;
        for (int c = 0; c < CHUNKS; ++c) s += sm->cnt[t * CHUNKS + c];
        sm->rowsum[t] = s;
        sm->sc[t] = s;
    }
    __syncthreads();

    // Parallel inclusive scan (Hillis-Steele, 9 steps), then exclusive offset.
    for (int off = 1; off < NKEYS; off <<= 1) {
        int v = 0;
        if (t < NKEYS && t >= off) v = sm->sc[t - off];
        __syncthreads();
        if (t < NKEYS) sm->sc[t] += v;
        __syncthreads();
    }
    if (t < NKEYS) sm->rowoff[t] = sm->sc[t] - sm->rowsum[t];
    __syncthreads();

#pragma unroll
    for (int p = 0; p < 2; ++p) {
        int idx = t + p * 1024;
        int key = mykey[p];
        unsigned mask = __match_any_sync(0xffffffffu, key);
        int intrarank = __popc(mask & ((1u << lane) - 1u));
        int cp = 0;
        for (int c = 0; c < (idx >> 5); ++c) cp += sm->cnt[key * CHUNKS + c];
        int pos = sm->rowoff[key] + cp + intrarank;
        if (idx < n) {
            ox[pos] = src[idx * 3 + 0];
            oy[pos] = src[idx * 3 + 1];
            oorig[pos] = idx;
        } else {
            ox[pos] = FAR_POISON;   // finite far poison: contributes exact 0
            oy[pos] = FAR_POISON;
            oorig[pos] = -1;
        }
    }
    __syncthreads();
}

__global__ void __launch_bounds__(1024) sort_kernel(
    const float* __restrict__ A, const float* __restrict__ B, int na, int nb)
{
    __shared__ SortSmem sm;
    counting_sort(&sm, A, na, g_Ax, g_Ay, g_Aorig);
    counting_sort(&sm, B, nb, g_Bx, g_By, g_Borig);

    // Per-j-tile bounding boxes over sorted B (real points only).
    int t = threadIdx.x;
    int ntiles = (nb + TILE_J - 1) / TILE_J;
    if (t < ntiles) {
        int j0 = t * TILE_J;
        int cnt = min(TILE_J, nb - j0);
        float mnx = 1e30f, mxx = -1e30f, mny = 1e30f, mxy = -1e30f;
        for (int k = 0; k < cnt; ++k) {
            float x = g_Bx[j0 + k], y = g_By[j0 + k];
            mnx = fminf(mnx, x); mxx = fmaxf(mxx, x);
            mny = fminf(mny, y); mxy = fmaxf(mxy, y);
        }
        g_Btile[t * 4 + 0] = mnx;
        g_Btile[t * 4 + 1] = mxx;
        g_Btile[t * 4 + 2] = mny;
        g_Btile[t * 4 + 3] = mxy;
    }
}

// ---------------------------------------------------------------------------
// Kernel 1: perimeter weights, thread-per-(i,b). Tiny body (no 50-bin trig
// unroll -> no I$ thrash), 76800 threads / 300 blocks. Mapping b = idx/na,
// i = idx%na -> reads of g_Ax/g_Ay and stores to g_wT[b][i] both coalesced.
// ---------------------------------------------------------------------------
__global__ void __launch_bounds__(256) weight_kernel(int na) {
    int idx = blockIdx.x * 256 + threadIdx.x;
    if (idx >= na * NBBINS) return;
    int b = idx / na;
    int i = idx - b * na;

    const float rmax = (float)rmax_d();
    const float TWO_PI = 6.283185307179586f;
    const float r = 0.1f * (float)(b + 1) * rmax;   // RS[b]

    float x = g_Ax[i], y = g_Ay[i];
    float full = TWO_PI;

    float sdx[4] = { x, 1.0f - x, y, 1.0f - y };
    float sdy[4] = { y, y,         x, x        };
    for (int s = 0; s < 4; ++s) {
        float dx = sdx[s], dy = sdy[s];
        if (r > dx) {                                // reference: RS > dx strict
            float ratio = fminf(dx / r, 1.0f);       // dx >= 0 always
            float alpha = acosf(ratio);
            float a1 = atan2f(dy, dx);
            float a2 = atan2f(1.0f - dy, dx);
            full -= fminf(alpha, a1) + fminf(alpha, a2);
        }
    }
    float per = fminf(fmaxf(full / TWO_PI, 0.0f), 1.0f);
    float w = fminf(1.0f / fmaxf(per, 1e-9f), 4.0f); // clip(w,0,4)
    g_wT[b * SORT_N + i] = w;
}

// ---------------------------------------------------------------------------
// Kernel 2: main accumulation, (sorted i) x (sorted j tile). Inner loop
// identical to the PASSING r13 kernel (1 SQRT + 50 EX2 per triggered pair;
// all poison paths finite). Epilogue: block partials via smem -> transposed
// g_partT[b][slot] so finalize reads coalesced.
// ---------------------------------------------------------------------------
__global__ void __launch_bounds__(TI) pcf_kernel(
    const int* __restrict__ same_cat, int na, int nb)
{
    __shared__ float sjx[TILE_J];
    __shared__ float sjy[TILE_J];
    __shared__ int   sjo[TILE_J];
    __shared__ float sw[2 * NBBINS];

    const int i = blockIdx.x * TI + threadIdx.x;
    const bool valid = (i < na);
    const int same = same_cat[0];

    const float L = 1.4426950408889634f;
    const float rmax = (float)rmax_d();
    const float s_scale = 4.0f / rmax;                   // d -> 4*d/RMAX
    const float thresh2 = (26.0f / s_scale) * (26.0f / s_scale);

    const float xi = valid ? g_Ax[i] : FAR_POISON;
    const float yi = valid ? g_Ay[i] : FAR_POISON;
    const int   oi = valid ? g_Aorig[i] : -1;

    float acc[NBBINS];
#pragma unroll
    for (int b = 0; b < NBBINS; ++b) acc[b] = 0.0f;

    const int tile = blockIdx.y;
    const int j0 = tile * TILE_J;
    const int cnt = min(TILE_J, nb - j0);

    if (threadIdx.x < cnt) {
        int j = j0 + threadIdx.x;
        sjx[threadIdx.x] = g_Bx[j];
        sjy[threadIdx.x] = g_By[j];
        sjo[threadIdx.x] = g_Borig[j];
    }
    __syncthreads();

    // Warp-vs-tile bbox prune.
    float bmnx = g_Btile[tile * 4 + 0];
    float bmxx = g_Btile[tile * 4 + 1];
    float bmny = g_Btile[tile * 4 + 2];
    float bmxy = g_Btile[tile * 4 + 3];
    float ddx = fmaxf(fmaxf(bmnx - xi, xi - bmxx), 0.0f);
    float ddy = fmaxf(fmaxf(bmny - yi, yi - bmxy), 0.0f);
    bool tile_near = !__all_sync(0xffffffffu, ddx * ddx + ddy * ddy > thresh2);

    if (tile_near) {
        for (int k = 0; k < cnt; ++k) {
            float dx = xi - sjx[k];
            float dy = yi - sjy[k];
            float d2 = dx * dx + dy * dy;

            if (__all_sync(0xffffffffu, d2 > thresh2)) continue;

            float s4 = sqrt_approx(d2) * s_scale;
            if (same && oi == sjo[k]) s4 = 3.0e18f;      // diagonal -> exact 0

            float P = L * s4 * s4;                       // finite on all paths
#pragma unroll
            for (int b = 0; b < NBBINS; ++b) {
                const float K1 = -L * 0.16f * (float)((b + 1) * (b + 1));
                const float K2 =  L * 0.80f * (float)(b + 1);
                acc[b] += ex2(fmaf(K2, s4, K1) - P);
            }
        }
    }

    // Weighted warp reduce -> smem -> one block partial per bin (deterministic).
    const int warp = threadIdx.x >> 5;
    const int iw = valid ? i : 0;
#pragma unroll
    for (int b = 0; b < NBBINS; ++b) {
        float wv = valid ? g_wT[b * SORT_N + iw] : 0.0f;   // coalesced
        float v = acc[b] * wv;
        v += __shfl_down_sync(0xffffffffu, v, 16);
        v += __shfl_down_sync(0xffffffffu, v, 8);
        v += __shfl_down_sync(0xffffffffu, v, 4);
        v += __shfl_down_sync(0xffffffffu, v, 2);
        v += __shfl_down_sync(0xffffffffu, v, 1);
        if ((threadIdx.x & 31) == 0) sw[warp * NBBINS + b] = v;
    }
    __syncthreads();
    if (threadIdx.x < NBBINS) {
        const int slot = blockIdx.y * gridDim.x + blockIdx.x;
        g_partT[threadIdx.x * PSLOTS + slot] =
            sw[threadIdx.x] + sw[NBBINS + threadIdx.x];
    }
}

// ---------------------------------------------------------------------------
// Kernel 3: deterministic reduction + normalization. One block per bin;
// partials transposed & contiguous -> fully coalesced reads.
// ---------------------------------------------------------------------------
__global__ void __launch_bounds__(256) finalize_kernel(
    float* __restrict__ out, int na, int nb, int nslots)
{
    __shared__ float red[256];
    const int b = blockIdx.x;
    const int t = threadIdx.x;

    float sum = 0.0f;
    for (int s = t; s < nslots; s += 256)
        sum += g_partT[b * PSLOTS + s];          // coalesced
    red[t] = sum;
    __syncthreads();
#pragma unroll
    for (int s = 128; s > 0; s >>= 1) {
        if (t < s) red[t] += red[t + s];
        __syncthreads();
    }

    if (t == 0) {
        double rmax = rmax_d();
        double rs = (double)(b + 1) * 0.1 * rmax;
        double inner = fmax(0.0, rs - 0.5 * rmax);
        double outer = rs + 0.5 * rmax;
        const double PI = 3.14159265358979323846;
        double area = PI * (outer * outer - inner * inner);
        double gf = 1.0 / (sqrt(PI) * 0.25);     // 1/(sqrt(pi)*SIGMA)

        double pcf1 = gf * (double)red[0] / (double)na / (area * (double)nb);
        out[2 * b + 0] = (float)(rs / rmax);
        out[2 * b + 1] = (float)pcf1;
    }
}

// ---------------------------------------------------------------------------
extern "C" void kernel_launch(void* const* d_in, const int* in_sizes, int n_in,
                              void* d_out, int out_size) {
    const float* A = (const float*)d_in[0];        // disks_a [na,3]
    const float* B = (const float*)d_in[1];        // disks_b [nb,3]
    const int* same = (const int*)d_in[2];         // same_category scalar
    float* out = (float*)d_out;                    // [NBBINS, 2]

    int na = in_sizes[0] / 3;
    int nb = in_sizes[1] / 3;

    sort_kernel<<<1, 1024>>>(A, B, na, nb);

    int wthreads = na * NBBINS;
    weight_kernel<<<(wthreads + 255) / 256, 256>>>(na);

    dim3 grid((na + TI - 1) / TI, (nb + TILE_J - 1) / TILE_J);
    pcf_kernel<<<grid, TI>>>(same, na, nb);

    int nslots = grid.x * grid.y;
    finalize_kernel<<<NBBINS, 256>>>(out, na, nb, nslots);
}

// round 16
// speedup vs baseline: 1.8140x; 1.8140x over previous
#include <cuda_runtime.h>
#include <math.h>

#define NBBINS 50
#define TI 64         // i-points per pcf block (= blockDim.x)
#define TILE_J 64     // j-points per block / per bbox tile
#define SORT_N 2048   // padded point count (na=nb=1536)
#define CHUNKS 64     // SORT_N / 32
#define NKEYS 257     // 256 morton cells + pad sentinel
#define MAXTILES (SORT_N / TILE_J)
#define PSLOTS 1024   // max pcf blocks (24x24=576 actual)
#define FAR_POISON 6.0e4f   // finite poison coords; s4 then clamps to 30 -> exact 0

// Scratch (device allocation forbidden).
__device__ float g_Ax[SORT_N];
__device__ float g_Ay[SORT_N];
__device__ int   g_Aorig[SORT_N];
__device__ float g_Bx[SORT_N];
__device__ float g_By[SORT_N];
__device__ int   g_Borig[SORT_N];
__device__ float g_Btile[MAXTILES * 4];        // minx, maxx, miny, maxy per j-tile
__device__ float g_wT[NBBINS * SORT_N];        // [b][i] transposed weights
__device__ float g_partT[NBBINS * PSLOTS];     // [b][slot] block partials

__device__ __forceinline__ double rmax_d() {
    // RMAX = 2*sqrt(1/(2*sqrt(3)*NPOINTS)), NPOINTS = 1536 in the reference.
    return 2.0 * sqrt(1.0 / (2.0 * sqrt(3.0) * 1536.0));
}

__device__ __forceinline__ unsigned spread4(unsigned v) {
    v = (v | (v << 2)) & 0x33u;
    v = (v | (v << 1)) & 0x55u;
    return v;
}

// Single MUFU.EX2; subnormal result flushed to exact 0 (ftz).
__device__ __forceinline__ float ex2(float x) {
    float r;
    asm("ex2.approx.ftz.f32 %0, %1;" : "=f"(r) : "f"(x));
    return r;
}
__device__ __forceinline__ float sqrt_approx(float x) {
    float r;
    asm("sqrt.approx.ftz.f32 %0, %1;" : "=f"(r) : "f"(x));
    return r;
}

// Packed f32x2 ops (Blackwell sm_103a).
typedef unsigned long long ull;
__device__ __forceinline__ ull pack2(float lo, float hi) {
    ull r; asm("mov.b64 %0, {%1, %2};" : "=l"(r) : "f"(lo), "f"(hi)); return r;
}
__device__ __forceinline__ void unpack2(ull v, float& lo, float& hi) {
    asm("mov.b64 {%0, %1}, %2;" : "=f"(lo), "=f"(hi) : "l"(v));
}
__device__ __forceinline__ ull mul2(ull a, ull b) {
    ull r; asm("mul.rn.f32x2 %0, %1, %2;" : "=l"(r) : "l"(a), "l"(b)); return r;
}
__device__ __forceinline__ ull add2(ull a, ull b) {
    ull r; asm("add.rn.f32x2 %0, %1, %2;" : "=l"(r) : "l"(a), "l"(b)); return r;
}

// ---------------------------------------------------------------------------
// Kernel 0: deterministic stable counting sort (16x16 Morton) of A AND B,
// plus per-j-tile bounding boxes for B. One block, 1024 threads.
// Parallel Hillis-Steele scan for the 257-key offsets.
// ---------------------------------------------------------------------------
struct SortSmem {
    unsigned char cnt[NKEYS * CHUNKS];
    int rowsum[NKEYS];
    int rowoff[NKEYS];
    int sc[NKEYS];
};

__device__ void counting_sort(SortSmem* sm, const float* __restrict__ src, int n,
                              float* ox, float* oy, int* oorig) {
    const int t = threadIdx.x;
    const int lane = t & 31;

    for (int k = t; k < NKEYS * CHUNKS; k += 1024) sm->cnt[k] = 0;
    __syncthreads();

    int mykey[2];
#pragma unroll
    for (int p = 0; p < 2; ++p) {
        int idx = t + p * 1024;
        int key = 256;                               // pad sentinel, sorts last
        if (idx < n) {
            float x = src[idx * 3 + 0];
            float y = src[idx * 3 + 1];
            int cx = min(15, max(0, (int)(x * 16.0f)));
            int cy = min(15, max(0, (int)(y * 16.0f)));
            key = (int)((spread4((unsigned)cy) << 1) | spread4((unsigned)cx));
        }
        mykey[p] = key;
        unsigned mask = __match_any_sync(0xffffffffu, key);
        if (lane == __ffs(mask) - 1)
            sm->cnt[key * CHUNKS + (idx >> 5)] = (unsigned char)__popc(mask);
    }
    __syncthreads();

    if (t < NKEYS) {
        int s = 0;
        for (int c = 0; c < CHUNKS; ++c) s += sm->cnt[t * CHUNKS + c];
        sm->rowsum[t] = s;
        sm->sc[t] = s;
    }
    __syncthreads();

    for (int off = 1; off < NKEYS; off <<= 1) {
        int v = 0;
        if (t < NKEYS && t >= off) v = sm->sc[t - off];
        __syncthreads();
        if (t < NKEYS) sm->sc[t] += v;
        __syncthreads();
    }
    if (t < NKEYS) sm->rowoff[t] = sm->sc[t] - sm->rowsum[t];
    __syncthreads();

#pragma unroll
    for (int p = 0; p < 2; ++p) {
        int idx = t + p * 1024;
        int key = mykey[p];
        unsigned mask = __match_any_sync(0xffffffffu, key);
        int intrarank = __popc(mask & ((1u << lane) - 1u));
        int cp = 0;
        for (int c = 0; c < (idx >> 5); ++c) cp += sm->cnt[key * CHUNKS + c];
        int pos = sm->rowoff[key] + cp + intrarank;
        if (idx < n) {
            ox[pos] = src[idx * 3 + 0];
            oy[pos] = src[idx * 3 + 1];
            oorig[pos] = idx;
        } else {
            ox[pos] = FAR_POISON;
            oy[pos] = FAR_POISON;
            oorig[pos] = -1;
        }
    }
    __syncthreads();
}

__global__ void __launch_bounds__(1024) sort_kernel(
    const float* __restrict__ A, const float* __restrict__ B, int na, int nb)
{
    __shared__ SortSmem sm;
    counting_sort(&sm, A, na, g_Ax, g_Ay, g_Aorig);
    counting_sort(&sm, B, nb, g_Bx, g_By, g_Borig);

    int t = threadIdx.x;
    int ntiles = (nb + TILE_J - 1) / TILE_J;
    if (t < ntiles) {
        int j0 = t * TILE_J;
        int cnt = min(TILE_J, nb - j0);
        float mnx = 1e30f, mxx = -1e30f, mny = 1e30f, mxy = -1e30f;
        for (int k = 0; k < cnt; ++k) {
            float x = g_Bx[j0 + k], y = g_By[j0 + k];
            mnx = fminf(mnx, x); mxx = fmaxf(mxx, x);
            mny = fminf(mny, y); mxy = fmaxf(mxy, y);
        }
        g_Btile[t * 4 + 0] = mnx;
        g_Btile[t * 4 + 1] = mxx;
        g_Btile[t * 4 + 2] = mny;
        g_Btile[t * 4 + 3] = mxy;
    }
}

// ---------------------------------------------------------------------------
// Kernel 1: perimeter weights, thread-per-(i,b). Tiny body, coalesced I/O.
// ---------------------------------------------------------------------------
__global__ void __launch_bounds__(256) weight_kernel(int na) {
    int idx = blockIdx.x * 256 + threadIdx.x;
    if (idx >= na * NBBINS) return;
    int b = idx / na;
    int i = idx - b * na;

    const float rmax = (float)rmax_d();
    const float TWO_PI = 6.283185307179586f;
    const float r = 0.1f * (float)(b + 1) * rmax;   // RS[b]

    float x = g_Ax[i], y = g_Ay[i];
    float full = TWO_PI;

    float sdx[4] = { x, 1.0f - x, y, 1.0f - y };
    float sdy[4] = { y, y,         x, x        };
    for (int s = 0; s < 4; ++s) {
        float dx = sdx[s], dy = sdy[s];
        if (r > dx) {                                // reference: RS > dx strict
            float ratio = fminf(dx / r, 1.0f);       // dx >= 0 always
            float alpha = acosf(ratio);
            float a1 = atan2f(dy, dx);
            float a2 = atan2f(1.0f - dy, dx);
            full -= fminf(alpha, a1) + fminf(alpha, a2);
        }
    }
    float per = fminf(fmaxf(full / TWO_PI, 0.0f), 1.0f);
    float w = fminf(1.0f / fmaxf(per, 1e-9f), 4.0f); // clip(w,0,4)
    g_wT[b * SORT_N + i] = w;
}

// ---------------------------------------------------------------------------
// Kernel 2: main accumulation with SEGMENTED GAUSSIAN RECURRENCE.
// u_b = 0.4(b+1) - s4;  v_b = exp(-u_b^2);  v_{b+1} = v_b * r_b;
// r_b = exp(-0.8u_b - 0.16);  r_{b+1} = r_b * C,  C = exp(-0.32).
// Bins packed (k, k+25) in f32x2; re-anchored at k=0 and k=13 (4 anchor
// points x 2 EX2 = 8 EX2/pair instead of 50).
// s4 clamped to 30 (also for diagonal): every clamped contribution has
// q <= -144 < -126 -> ex2.ftz underflows to EXACT 0. All intermediates
// finite (max ratio 2^33.9). Wrongly-zeroed anchor-underflow terms
// < e^-17 each -> rel impact < 1e-6.
// ---------------------------------------------------------------------------
__global__ void __launch_bounds__(TI) pcf_kernel(
    const int* __restrict__ same_cat, int na, int nb)
{
    __shared__ float sjx[TILE_J];
    __shared__ float sjy[TILE_J];
    __shared__ int   sjo[TILE_J];
    __shared__ float sw[2 * NBBINS];

    const int i = blockIdx.x * TI + threadIdx.x;
    const bool valid = (i < na);
    const int same = same_cat[0];

    const float L = 1.4426950408889634f;           // log2(e)
    const float CR = 0.7261490370736909f;          // exp(-0.32)
    const float rmax = (float)rmax_d();
    const float s_scale = 4.0f / rmax;             // d -> 4*d/RMAX
    const float thresh2 = (26.0f / s_scale) * (26.0f / s_scale);

    const float xi = valid ? g_Ax[i] : FAR_POISON;
    const float yi = valid ? g_Ay[i] : FAR_POISON;
    const int   oi = valid ? g_Aorig[i] : -1;

    const ull C2 = pack2(CR, CR);

    ull acc2[25];
#pragma unroll
    for (int k = 0; k < 25; ++k) acc2[k] = 0ull;   // packed (0.0f, 0.0f)

    const int tile = blockIdx.y;
    const int j0 = tile * TILE_J;
    const int cnt = min(TILE_J, nb - j0);

    if (threadIdx.x < cnt) {
        int j = j0 + threadIdx.x;
        sjx[threadIdx.x] = g_Bx[j];
        sjy[threadIdx.x] = g_By[j];
        sjo[threadIdx.x] = g_Borig[j];
    }
    __syncthreads();

    // Warp-vs-tile bbox prune.
    float bmnx = g_Btile[tile * 4 + 0];
    float bmxx = g_Btile[tile * 4 + 1];
    float bmny = g_Btile[tile * 4 + 2];
    float bmxy = g_Btile[tile * 4 + 3];
    float ddx = fmaxf(fmaxf(bmnx - xi, xi - bmxx), 0.0f);
    float ddy = fmaxf(fmaxf(bmny - yi, yi - bmxy), 0.0f);
    bool tile_near = !__all_sync(0xffffffffu, ddx * ddx + ddy * ddy > thresh2);

    if (tile_near) {
        for (int k = 0; k < cnt; ++k) {
            float dx = xi - sjx[k];
            float dy = yi - sjy[k];
            float d2 = dx * dx + dy * dy;

            if (__all_sync(0xffffffffu, d2 > thresh2)) continue;

            float s4 = fminf(sqrt_approx(d2) * s_scale, 30.0f);
            if (same && oi == sjo[k]) s4 = 30.0f;  // diagonal -> exact 0 path

            const float u0 = 0.4f - s4;            // u at bin 0

            // anchors: bins 0 & 25 (u0, u0+10), re-anchor at 13 & 38.
            float ua0 = u0, ua1 = u0 + 10.0f;
            float v0 = ex2(-L * ua0 * ua0);
            float v1 = ex2(-L * ua1 * ua1);
            float r0 = ex2(L * fmaf(-0.8f, ua0, -0.16f));
            float r1 = ex2(L * fmaf(-0.8f, ua1, -0.16f));
            ull v2 = pack2(v0, v1);
            ull r2 = pack2(r0, r1);

#pragma unroll
            for (int kk = 0; kk < 25; ++kk) {
                if (kk == 13) {                    // re-anchor (compile-time)
                    float ub0 = u0 + 5.2f, ub1 = u0 + 15.2f;
                    float w0 = ex2(-L * ub0 * ub0);
                    float w1 = ex2(-L * ub1 * ub1);
                    float s0 = ex2(L * fmaf(-0.8f, ub0, -0.16f));
                    float s1 = ex2(L * fmaf(-0.8f, ub1, -0.16f));
                    v2 = pack2(w0, w1);
                    r2 = pack2(s0, s1);
                }
                acc2[kk] = add2(acc2[kk], v2);
                v2 = mul2(v2, r2);
                r2 = mul2(r2, C2);
            }
        }
    }

    // Weighted warp reduce -> smem -> one block partial per bin.
    const int warp = threadIdx.x >> 5;
    const int iw = valid ? i : 0;
#pragma unroll
    for (int kk = 0; kk < 25; ++kk) {
        float alo, ahi;
        unpack2(acc2[kk], alo, ahi);
#pragma unroll
        for (int h = 0; h < 2; ++h) {
            int b = kk + h * 25;
            float a = h ? ahi : alo;
            float wv = valid ? g_wT[b * SORT_N + iw] : 0.0f;   // coalesced
            float v = a * wv;
            v += __shfl_down_sync(0xffffffffu, v, 16);
            v += __shfl_down_sync(0xffffffffu, v, 8);
            v += __shfl_down_sync(0xffffffffu, v, 4);
            v += __shfl_down_sync(0xffffffffu, v, 2);
            v += __shfl_down_sync(0xffffffffu, v, 1);
            if ((threadIdx.x & 31) == 0) sw[warp * NBBINS + b] = v;
        }
    }
    __syncthreads();
    if (threadIdx.x < NBBINS) {
        const int slot = blockIdx.y * gridDim.x + blockIdx.x;
        g_partT[threadIdx.x * PSLOTS + slot] =
            sw[threadIdx.x] + sw[NBBINS + threadIdx.x];
    }
}

// ---------------------------------------------------------------------------
// Kernel 3: deterministic reduction + normalization. One block per bin;
// partials transposed & contiguous -> coalesced reads.
// ---------------------------------------------------------------------------
__global__ void __launch_bounds__(256) finalize_kernel(
    float* __restrict__ out, int na, int nb, int nslots)
{
    __shared__ float red[256];
    const int b = blockIdx.x;
    const int t = threadIdx.x;

    float sum = 0.0f;
    for (int s = t; s < nslots; s += 256)
        sum += g_partT[b * PSLOTS + s];
    red[t] = sum;
    __syncthreads();
#pragma unroll
    for (int s = 128; s > 0; s >>= 1) {
        if (t < s) red[t] += red[t + s];
        __syncthreads();
    }

    if (t == 0) {
        double rmax = rmax_d();
        double rs = (double)(b + 1) * 0.1 * rmax;
        double inner = fmax(0.0, rs - 0.5 * rmax);
        double outer = rs + 0.5 * rmax;
        const double PI = 3.14159265358979323846;
        double area = PI * (outer * outer - inner * inner);
        double gf = 1.0 / (sqrt(PI) * 0.25);     // 1/(sqrt(pi)*SIGMA)

        double pcf1 = gf * (double)red[0] / (double)na / (area * (double)nb);
        out[2 * b + 0] = (float)(rs / rmax);
        out[2 * b + 1] = (float)pcf1;
    }
}

// ---------------------------------------------------------------------------
extern "C" void kernel_launch(void* const* d_in, const int* in_sizes, int n_in,
                              void* d_out, int out_size) {
    const float* A = (const float*)d_in[0];        // disks_a [na,3]
    const float* B = (const float*)d_in[1];        // disks_b [nb,3]
    const int* same = (const int*)d_in[2];         // same_category scalar
    float* out = (float*)d_out;                    // [NBBINS, 2]

    int na = in_sizes[0] / 3;
    int nb = in_sizes[1] / 3;

    sort_kernel<<<1, 1024>>>(A, B, na, nb);

    int wthreads = na * NBBINS;
    weight_kernel<<<(wthreads + 255) / 256, 256>>>(na);

    dim3 grid((na + TI - 1) / TI, (nb + TILE_J - 1) / TILE_J);
    pcf_kernel<<<grid, TI>>>(same, na, nb);

    int nslots = grid.x * grid.y;
    finalize_kernel<<<NBBINS, 256>>>(out, na, nb, nslots);
}